// round 1
// baseline (speedup 1.0000x reference)
#include <cuda_runtime.h>
#include <cuda_bf16.h>
#include <math.h>

// ---------------------------------------------------------------------------
// Problem constants
// ---------------------------------------------------------------------------
#define PATCH     16
#define IMG       384
#define DMODEL    768
#define DMLP      3072
#define NLAYERS   12
#define NHEADS    12
#define DHEAD     64
#define NCLASSES  1000
#define BATCH     64
#define NPATCH    576              // (384/16)^2
#define NTOK      577              // NPATCH + 1
#define TTOK      (BATCH * NTOK)   // 36928 total token rows
#define TPAT      (BATCH * NPATCH) // 36864 patch rows
#define QKV3      (3 * DMODEL)     // 2304

// ---------------------------------------------------------------------------
// Scratch (device globals: allocation inside kernel_launch is forbidden)
// ---------------------------------------------------------------------------
__device__ float g_z  [(size_t)TTOK * DMODEL];   // residual stream
__device__ float g_h  [(size_t)TTOK * DMODEL];   // LN output
__device__ float g_qkv[(size_t)TTOK * QKV3];     // qkv (also reused as im2col buffer)
__device__ float g_att[(size_t)TTOK * DMODEL];   // attention output
__device__ float g_mlp[(size_t)TTOK * DMLP];     // mlp hidden
__device__ float g_y  [(size_t)BATCH * DMODEL];  // cls LN output
__device__ float g_t1 [(size_t)BATCH * DMLP];    // head hidden

// ---------------------------------------------------------------------------
// Helpers
// ---------------------------------------------------------------------------
__device__ __forceinline__ float gelu_exact(float x) {
    return 0.5f * x * (1.0f + erff(x * 0.70710678118654752f));
}

// ---------------------------------------------------------------------------
// GEMM: C = epi(A[M,K] @ B[K,N] + bias) (+ residual)
// EPI: 0 = bias only
//      1 = gelu(acc + bias)
//      2 = acc + bias + Res[r,c]                 (top proj residual)
//      3 = gelu(acc + bias) + Res[r,c]           (mlp2 residual)
//      4 = acc + bias + pose, remapped rows      (patch embed -> z)
// 128x128 tile, BK=16, 256 threads, 8x8 per thread, double-buffered smem.
// ---------------------------------------------------------------------------
#define BM 128
#define BN 128
#define BKT 16

template<int EPI>
__global__ __launch_bounds__(256, 2)
void gemm_kernel(const float* __restrict__ A, const float* __restrict__ B,
                 const float* __restrict__ bias, const float* Res,
                 float* C, int M, int N, int K)
{
    __shared__ float As[2][BKT][BM];
    __shared__ float Bs[2][BKT][BN];

    const int tid  = threadIdx.x;
    const int tc   = tid & 15;       // 0..15 col group
    const int tr   = tid >> 4;       // 0..15 row group
    const int row0 = blockIdx.y * BM;
    const int col0 = blockIdx.x * BN;

    // global load mapping
    const int ar = tid >> 2;          // 0..63   (A rows; +64 for 2nd load)
    const int ac = (tid & 3) * 4;     // 0,4,8,12 (A k offset)
    const int br = tid >> 5;          // 0..7    (B rows; +8 for 2nd load)
    const int bc = (tid & 31) * 4;    // 0..124  (B col offset)

    const float4 z4 = make_float4(0.f, 0.f, 0.f, 0.f);

    float acc[8][8];
#pragma unroll
    for (int i = 0; i < 8; i++)
#pragma unroll
        for (int j = 0; j < 8; j++) acc[i][j] = 0.f;

    // ---- load tile 0 ----
    {
        const int r1 = row0 + ar, r2 = row0 + ar + 64;
        float4 a0 = (r1 < M) ? *(const float4*)(A + (size_t)r1 * K + ac) : z4;
        float4 a1 = (r2 < M) ? *(const float4*)(A + (size_t)r2 * K + ac) : z4;
        As[0][ac + 0][ar] = a0.x; As[0][ac + 1][ar] = a0.y;
        As[0][ac + 2][ar] = a0.z; As[0][ac + 3][ar] = a0.w;
        As[0][ac + 0][ar + 64] = a1.x; As[0][ac + 1][ar + 64] = a1.y;
        As[0][ac + 2][ar + 64] = a1.z; As[0][ac + 3][ar + 64] = a1.w;
        const int c = col0 + bc;
        float4 b0 = z4, b1 = z4;
        if (c < N) {
            b0 = *(const float4*)(B + (size_t)br * N + c);
            b1 = *(const float4*)(B + (size_t)(br + 8) * N + c);
        }
        *(float4*)&Bs[0][br][bc]     = b0;
        *(float4*)&Bs[0][br + 8][bc] = b1;
    }
    __syncthreads();

    const int ntile = K / BKT;
    int buf = 0;
    float4 pa0, pa1, pb0, pb1;

    for (int t = 0; t < ntile; ++t) {
        if (t + 1 < ntile) {
            const int kt = (t + 1) * BKT;
            const int r1 = row0 + ar, r2 = row0 + ar + 64;
            pa0 = (r1 < M) ? *(const float4*)(A + (size_t)r1 * K + kt + ac) : z4;
            pa1 = (r2 < M) ? *(const float4*)(A + (size_t)r2 * K + kt + ac) : z4;
            const int c = col0 + bc;
            if (c < N) {
                pb0 = *(const float4*)(B + (size_t)(kt + br) * N + c);
                pb1 = *(const float4*)(B + (size_t)(kt + br + 8) * N + c);
            } else { pb0 = z4; pb1 = z4; }
        }
#pragma unroll
        for (int kk = 0; kk < BKT; ++kk) {
            float4 a0 = *(const float4*)&As[buf][kk][tr * 4];
            float4 a1 = *(const float4*)&As[buf][kk][64 + tr * 4];
            float4 b0 = *(const float4*)&Bs[buf][kk][tc * 4];
            float4 b1 = *(const float4*)&Bs[buf][kk][64 + tc * 4];
            float av[8] = {a0.x, a0.y, a0.z, a0.w, a1.x, a1.y, a1.z, a1.w};
            float bv[8] = {b0.x, b0.y, b0.z, b0.w, b1.x, b1.y, b1.z, b1.w};
#pragma unroll
            for (int i = 0; i < 8; i++)
#pragma unroll
                for (int j = 0; j < 8; j++)
                    acc[i][j] = fmaf(av[i], bv[j], acc[i][j]);
        }
        if (t + 1 < ntile) {
            buf ^= 1;
            As[buf][ac + 0][ar] = pa0.x; As[buf][ac + 1][ar] = pa0.y;
            As[buf][ac + 2][ar] = pa0.z; As[buf][ac + 3][ar] = pa0.w;
            As[buf][ac + 0][ar + 64] = pa1.x; As[buf][ac + 1][ar + 64] = pa1.y;
            As[buf][ac + 2][ar + 64] = pa1.z; As[buf][ac + 3][ar + 64] = pa1.w;
            *(float4*)&Bs[buf][br][bc]     = pb0;
            *(float4*)&Bs[buf][br + 8][bc] = pb1;
            __syncthreads();
        }
    }

    // ---- epilogue ----
#pragma unroll
    for (int ih = 0; ih < 2; ih++) {
#pragma unroll
        for (int ii = 0; ii < 4; ii++) {
            const int r = row0 + ih * 64 + tr * 4 + ii;
            if (r >= M) continue;
            size_t obase;
            const float* resrow = nullptr;
            if (EPI == 4) {
                const int bb = r / NPATCH, nn = r - bb * NPATCH;
                obase  = ((size_t)bb * NTOK + nn + 1) * (size_t)N;
                resrow = Res + (size_t)(nn + 1) * N;   // pose_embed row
            } else {
                obase = (size_t)r * N;
            }
#pragma unroll
            for (int jh = 0; jh < 2; jh++) {
                const int ccol = col0 + jh * 64 + tc * 4;
                if (ccol >= N) continue;
                const float4 bv = *(const float4*)(bias + ccol);
                float v[4] = {acc[ih * 4 + ii][jh * 4 + 0] + bv.x,
                              acc[ih * 4 + ii][jh * 4 + 1] + bv.y,
                              acc[ih * 4 + ii][jh * 4 + 2] + bv.z,
                              acc[ih * 4 + ii][jh * 4 + 3] + bv.w};
                if (EPI == 1 || EPI == 3) {
#pragma unroll
                    for (int jj = 0; jj < 4; jj++) v[jj] = gelu_exact(v[jj]);
                }
                if (EPI == 2 || EPI == 3) {
                    const float4 rv = *(const float4*)(Res + (size_t)r * N + ccol);
                    v[0] += rv.x; v[1] += rv.y; v[2] += rv.z; v[3] += rv.w;
                }
                if (EPI == 4) {
                    const float4 rv = *(const float4*)(resrow + ccol);
                    v[0] += rv.x; v[1] += rv.y; v[2] += rv.z; v[3] += rv.w;
                }
                *(float4*)(C + obase + ccol) = make_float4(v[0], v[1], v[2], v[3]);
            }
        }
    }
}

// ---------------------------------------------------------------------------
// LayerNorm: warp per row, D=768 (24 elems/lane). xstride allows strided
// gather of the cls rows for the final LN.
// ---------------------------------------------------------------------------
__global__ __launch_bounds__(256)
void ln_kernel(const float* __restrict__ X, size_t xstride,
               const float* __restrict__ w, const float* __restrict__ b,
               float* __restrict__ Y, int rows)
{
    const int warp = threadIdx.x >> 5;
    const int lane = threadIdx.x & 31;
    const int row  = blockIdx.x * 8 + warp;
    if (row >= rows) return;
    const float* xr = X + (size_t)row * xstride;
    float v[24];
    float s = 0.f, sq = 0.f;
#pragma unroll
    for (int j = 0; j < 24; j++) {
        v[j] = xr[lane + 32 * j];
        s  += v[j];
        sq += v[j] * v[j];
    }
#pragma unroll
    for (int o = 16; o; o >>= 1) {
        s  += __shfl_xor_sync(0xffffffffu, s,  o);
        sq += __shfl_xor_sync(0xffffffffu, sq, o);
    }
    const float mean = s * (1.0f / DMODEL);
    const float var  = sq * (1.0f / DMODEL) - mean * mean;
    const float rstd = rsqrtf(var + 1e-5f);
#pragma unroll
    for (int j = 0; j < 24; j++) {
        const int d = lane + 32 * j;
        Y[(size_t)row * DMODEL + d] = (v[j] - mean) * rstd * w[d] + b[d];
    }
}

// ---------------------------------------------------------------------------
// Per-token head attention: 12x12 softmax over heads per token.
// Block = 12 warps = 1 token; warp h computes output head h.
// ---------------------------------------------------------------------------
__global__ __launch_bounds__(384)
void attn_kernel(const float* __restrict__ QKV, float* __restrict__ O)
{
    const int token = blockIdx.x;
    const int h     = threadIdx.x >> 5;   // 0..11
    const int lane  = threadIdx.x & 31;
    const float* base = QKV + (size_t)token * QKV3;

    const float2 q = *(const float2*)(base + h * DHEAD + 2 * lane);
    float s[NHEADS];
#pragma unroll
    for (int g = 0; g < NHEADS; g++) {
        const float2 kv = *(const float2*)(base + DMODEL + g * DHEAD + 2 * lane);
        float p = q.x * kv.x + q.y * kv.y;
#pragma unroll
        for (int o = 16; o; o >>= 1) p += __shfl_xor_sync(0xffffffffu, p, o);
        s[g] = p * 0.125f;   // / sqrt(64)
    }
    float m = s[0];
#pragma unroll
    for (int g = 1; g < NHEADS; g++) m = fmaxf(m, s[g]);
    float sum = 0.f;
#pragma unroll
    for (int g = 0; g < NHEADS; g++) { s[g] = expf(s[g] - m); sum += s[g]; }
    const float inv = 1.0f / sum;
    float o0 = 0.f, o1 = 0.f;
#pragma unroll
    for (int g = 0; g < NHEADS; g++) {
        const float2 vv = *(const float2*)(base + 2 * DMODEL + g * DHEAD + 2 * lane);
        const float a = s[g] * inv;
        o0 += a * vv.x;
        o1 += a * vv.y;
    }
    *(float2*)(O + (size_t)token * DMODEL + h * DHEAD + 2 * lane) = make_float2(o0, o1);
}

// ---------------------------------------------------------------------------
// im2col: x(B,3,384,384) -> patches (B*576, 768) with (C,Ph,Pw) inner order
// ---------------------------------------------------------------------------
__global__ __launch_bounds__(256)
void im2col_kernel(const float* __restrict__ X, float* __restrict__ P)
{
    const long long idx = (long long)blockIdx.x * 256 + threadIdx.x;
    if (idx >= (long long)TPAT * DMODEL) return;
    const int k = (int)(idx % DMODEL);
    const int r = (int)(idx / DMODEL);
    const int b = r / NPATCH, n = r - b * NPATCH;
    const int py = n / (IMG / PATCH), px = n - py * (IMG / PATCH);
    const int c = k / (PATCH * PATCH);
    const int rem = k - c * (PATCH * PATCH);
    const int ph = rem / PATCH, pw = rem - ph * PATCH;
    P[idx] = X[(((size_t)b * 3 + c) * IMG + (py * PATCH + ph)) * IMG + (px * PATCH + pw)];
}

// ---------------------------------------------------------------------------
// cls row init: z[b, 0, :] = class_embed + pose_embed[0]
// ---------------------------------------------------------------------------
__global__ __launch_bounds__(256)
void cls_init_kernel(const float* __restrict__ ce, const float* __restrict__ pe,
                     float* __restrict__ Z)
{
    const int i = blockIdx.x * 256 + threadIdx.x;
    if (i >= BATCH * DMODEL) return;
    const int d = i % DMODEL, b = i / DMODEL;
    Z[(size_t)b * NTOK * DMODEL + d] = ce[d] + pe[d];
}

// ---------------------------------------------------------------------------
// Host launch
// ---------------------------------------------------------------------------
extern "C" void kernel_launch(void* const* d_in, const int* in_sizes, int n_in,
                              void* d_out, int out_size)
{
    (void)in_sizes; (void)n_in; (void)out_size;
    const float* x       = (const float*)d_in[0];
    const float* ce      = (const float*)d_in[1];
    const float* pose    = (const float*)d_in[2];
    const float* proj_w  = (const float*)d_in[3];
    const float* proj_b  = (const float*)d_in[4];
    const float* qkv_w   = (const float*)d_in[5];
    const float* qkv_b   = (const float*)d_in[6];
    const float* top_w   = (const float*)d_in[7];
    const float* top_b   = (const float*)d_in[8];
    const float* ln1_w   = (const float*)d_in[9];
    const float* ln1_b   = (const float*)d_in[10];
    const float* ln2_w   = (const float*)d_in[11];
    const float* ln2_b   = (const float*)d_in[12];
    const float* mlp_w1  = (const float*)d_in[13];
    const float* mlp_b1  = (const float*)d_in[14];
    const float* mlp_w2  = (const float*)d_in[15];
    const float* mlp_b2  = (const float*)d_in[16];
    const float* ln3_w   = (const float*)d_in[17];
    const float* ln3_b   = (const float*)d_in[18];
    const float* head_w1 = (const float*)d_in[19];
    const float* head_b1 = (const float*)d_in[20];
    const float* head_w2 = (const float*)d_in[21];
    const float* head_b2 = (const float*)d_in[22];
    float* out = (float*)d_out;

    float *zp, *hp, *qkvp, *attp, *mlpp, *yp, *t1p;
    cudaGetSymbolAddress((void**)&zp,   g_z);
    cudaGetSymbolAddress((void**)&hp,   g_h);
    cudaGetSymbolAddress((void**)&qkvp, g_qkv);
    cudaGetSymbolAddress((void**)&attp, g_att);
    cudaGetSymbolAddress((void**)&mlpp, g_mlp);
    cudaGetSymbolAddress((void**)&yp,   g_y);
    cudaGetSymbolAddress((void**)&t1p,  g_t1);

    // ---- patch embedding ----
    {
        const long long tot = (long long)TPAT * DMODEL;
        im2col_kernel<<<(unsigned)((tot + 255) / 256), 256>>>(x, qkvp);
        cls_init_kernel<<<(BATCH * DMODEL + 255) / 256, 256>>>(ce, pose, zp);
        dim3 grid(DMODEL / BN, (TPAT + BM - 1) / BM);
        gemm_kernel<4><<<grid, 256>>>(qkvp, proj_w, proj_b, pose, zp,
                                      TPAT, DMODEL, DMODEL);
    }

    const int lnGrid = (TTOK + 7) / 8;

    for (int i = 0; i < NLAYERS; i++) {
        // LN1
        ln_kernel<<<lnGrid, 256>>>(zp, DMODEL, ln1_w + (size_t)i * DMODEL,
                                   ln1_b + (size_t)i * DMODEL, hp, TTOK);
        // QKV
        {
            dim3 grid(QKV3 / BN, (TTOK + BM - 1) / BM);
            gemm_kernel<0><<<grid, 256>>>(hp, qkv_w + (size_t)i * DMODEL * QKV3,
                                          qkv_b + (size_t)i * QKV3, nullptr, qkvp,
                                          TTOK, QKV3, DMODEL);
        }
        // per-token head attention
        attn_kernel<<<TTOK, 384>>>(qkvp, attp);
        // top projection + residual -> z
        {
            dim3 grid(DMODEL / BN, (TTOK + BM - 1) / BM);
            gemm_kernel<2><<<grid, 256>>>(attp, top_w + (size_t)i * DMODEL * DMODEL,
                                          top_b + (size_t)i * DMODEL, zp, zp,
                                          TTOK, DMODEL, DMODEL);
        }
        // LN2
        ln_kernel<<<lnGrid, 256>>>(zp, DMODEL, ln2_w + (size_t)i * DMODEL,
                                   ln2_b + (size_t)i * DMODEL, hp, TTOK);
        // MLP1 (gelu)
        {
            dim3 grid(DMLP / BN, (TTOK + BM - 1) / BM);
            gemm_kernel<1><<<grid, 256>>>(hp, mlp_w1 + (size_t)i * DMODEL * DMLP,
                                          mlp_b1 + (size_t)i * DMLP, nullptr, mlpp,
                                          TTOK, DMLP, DMODEL);
        }
        // MLP2 (gelu) + residual -> z
        {
            dim3 grid(DMODEL / BN, (TTOK + BM - 1) / BM);
            gemm_kernel<3><<<grid, 256>>>(mlpp, mlp_w2 + (size_t)i * DMLP * DMODEL,
                                          mlp_b2 + (size_t)i * DMODEL, zp, zp,
                                          TTOK, DMODEL, DMLP);
        }
    }

    // ---- classification head ----
    ln_kernel<<<(BATCH + 7) / 8, 256>>>(zp, (size_t)NTOK * DMODEL, ln3_w, ln3_b,
                                        yp, BATCH);
    {
        dim3 grid(DMLP / BN, (BATCH + BM - 1) / BM);
        gemm_kernel<1><<<grid, 256>>>(yp, head_w1, head_b1, nullptr, t1p,
                                      BATCH, DMLP, DMODEL);
    }
    {
        dim3 grid((NCLASSES + BN - 1) / BN, (BATCH + BM - 1) / BM);
        gemm_kernel<1><<<grid, 256>>>(t1p, head_w2, head_b2, nullptr, out,
                                      BATCH, NCLASSES, DMLP);
    }
}

// round 2
// speedup vs baseline: 1.0687x; 1.0687x over previous
#include <cuda_runtime.h>
#include <cuda_bf16.h>
#include <math.h>
#include <stdint.h>

// ---------------------------------------------------------------------------
// Problem constants
// ---------------------------------------------------------------------------
#define PATCH     16
#define IMG       384
#define DMODEL    768
#define DMLP      3072
#define NLAYERS   12
#define NHEADS    12
#define DHEAD     64
#define NCLASSES  1000
#define BATCH     64
#define NPATCH    576
#define NTOK      577
#define TTOK      (BATCH * NTOK)   // 36928
#define TPAT      (BATCH * NPATCH) // 36864
#define QKV3      (3 * DMODEL)     // 2304

// ---------------------------------------------------------------------------
// Scratch
// ---------------------------------------------------------------------------
__device__ float g_z  [(size_t)TTOK * DMODEL];
__device__ float g_h  [(size_t)TTOK * DMODEL];
__device__ float g_qkv[(size_t)TTOK * QKV3];
__device__ float g_att[(size_t)TTOK * DMODEL];
__device__ float g_mlp[(size_t)TTOK * DMLP];
__device__ float g_y  [(size_t)BATCH * DMODEL];
__device__ float g_t1 [(size_t)BATCH * DMLP];

// ---------------------------------------------------------------------------
// Helpers
// ---------------------------------------------------------------------------
__device__ __forceinline__ float gelu_exact(float x) {
    return 0.5f * x * (1.0f + erff(x * 0.70710678118654752f));
}

__device__ __forceinline__ void f32_split_tf32(float x, uint32_t& hi, uint32_t& lo) {
    asm("cvt.rna.tf32.f32 %0, %1;" : "=r"(hi) : "f"(x));
    float hif = __uint_as_float(hi);
    asm("cvt.rna.tf32.f32 %0, %1;" : "=r"(lo) : "f"(x - hif));
}

__device__ __forceinline__ void mma_tf32(float c[4], uint32_t a0, uint32_t a1,
                                         uint32_t a2, uint32_t a3,
                                         uint32_t b0, uint32_t b1) {
    asm volatile(
        "mma.sync.aligned.m16n8k8.row.col.f32.tf32.tf32.f32 "
        "{%0,%1,%2,%3}, {%4,%5,%6,%7}, {%8,%9}, {%0,%1,%2,%3};\n"
        : "+f"(c[0]), "+f"(c[1]), "+f"(c[2]), "+f"(c[3])
        : "r"(a0), "r"(a1), "r"(a2), "r"(a3), "r"(b0), "r"(b1));
}

// ---------------------------------------------------------------------------
// Tensor-core GEMM (3xTF32): C = epi(A[M,K] @ B[K,N] + bias) (+ residual)
// EPI: 0 bias | 1 gelu | 2 bias+res | 3 gelu+res | 4 bias+pose(remapped rows)
// Block 128x128xBK16, 256 threads, 8 warps of 64x32 (m16n8k8 tiles).
// ---------------------------------------------------------------------------
#define BM 128
#define BN 128
#define BKT 16
#define APAD 8
#define ASTR (BM + APAD)
#define BSTR (BN + APAD)

template<int EPI>
__global__ __launch_bounds__(256)
void gemm_tc(const float* __restrict__ A, const float* __restrict__ B,
             const float* __restrict__ bias, const float* Res,
             float* C, int M, int N, int K)
{
    __shared__ float As[2][BKT][ASTR];
    __shared__ float Bs[2][BKT][BSTR];

    const int tid  = threadIdx.x;
    const int lane = tid & 31;
    const int warp = tid >> 5;
    const int wm   = warp >> 2;   // 0..1  (64-row slab)
    const int wn   = warp & 3;    // 0..3  (32-col slab)
    const int g    = lane >> 2;   // groupID 0..7
    const int tg   = lane & 3;    // 0..3

    const int row0 = blockIdx.y * BM;
    const int col0 = blockIdx.x * BN;

    // global->smem mapping
    const int ar = tid >> 2;          // 0..63 (A rows, +64 second)
    const int ac = (tid & 3) * 4;     // k offset
    const int br = tid >> 5;          // 0..7  (B k rows, +8 second)
    const int bc = (tid & 31) * 4;    // col offset

    const float4 z4 = make_float4(0.f, 0.f, 0.f, 0.f);

    float acc[4][4][4];
#pragma unroll
    for (int i = 0; i < 4; i++)
#pragma unroll
        for (int j = 0; j < 4; j++)
#pragma unroll
            for (int q = 0; q < 4; q++) acc[i][j][q] = 0.f;

    // ---- load tile 0 ----
    {
        const int r1 = row0 + ar, r2 = row0 + ar + 64;
        float4 a0 = (r1 < M) ? *(const float4*)(A + (size_t)r1 * K + ac) : z4;
        float4 a1 = (r2 < M) ? *(const float4*)(A + (size_t)r2 * K + ac) : z4;
        As[0][ac + 0][ar] = a0.x; As[0][ac + 1][ar] = a0.y;
        As[0][ac + 2][ar] = a0.z; As[0][ac + 3][ar] = a0.w;
        As[0][ac + 0][ar + 64] = a1.x; As[0][ac + 1][ar + 64] = a1.y;
        As[0][ac + 2][ar + 64] = a1.z; As[0][ac + 3][ar + 64] = a1.w;
        const int c = col0 + bc;
        float4 b0 = z4, b1 = z4;
        if (c < N) {
            b0 = *(const float4*)(B + (size_t)br * N + c);
            b1 = *(const float4*)(B + (size_t)(br + 8) * N + c);
        }
        *(float4*)&Bs[0][br][bc]     = b0;
        *(float4*)&Bs[0][br + 8][bc] = b1;
    }
    __syncthreads();

    const int ntile = K / BKT;
    int buf = 0;
    float4 pa0, pa1, pb0, pb1;

    for (int t = 0; t < ntile; ++t) {
        if (t + 1 < ntile) {
            const int kt = (t + 1) * BKT;
            const int r1 = row0 + ar, r2 = row0 + ar + 64;
            pa0 = (r1 < M) ? *(const float4*)(A + (size_t)r1 * K + kt + ac) : z4;
            pa1 = (r2 < M) ? *(const float4*)(A + (size_t)r2 * K + kt + ac) : z4;
            const int c = col0 + bc;
            if (c < N) {
                pb0 = *(const float4*)(B + (size_t)(kt + br) * N + c);
                pb1 = *(const float4*)(B + (size_t)(kt + br + 8) * N + c);
            } else { pb0 = z4; pb1 = z4; }
        }

#pragma unroll
        for (int ks = 0; ks < 2; ks++) {
            const int kb = ks * 8;
            uint32_t ahi[4][4], alo[4][4];
#pragma unroll
            for (int mi = 0; mi < 4; mi++) {
                const int r = wm * 64 + mi * 16 + g;
                float x0 = As[buf][kb + tg    ][r];
                float x1 = As[buf][kb + tg    ][r + 8];
                float x2 = As[buf][kb + tg + 4][r];
                float x3 = As[buf][kb + tg + 4][r + 8];
                f32_split_tf32(x0, ahi[mi][0], alo[mi][0]);
                f32_split_tf32(x1, ahi[mi][1], alo[mi][1]);
                f32_split_tf32(x2, ahi[mi][2], alo[mi][2]);
                f32_split_tf32(x3, ahi[mi][3], alo[mi][3]);
            }
            uint32_t bhi[4][2], blo[4][2];
#pragma unroll
            for (int ni = 0; ni < 4; ni++) {
                const int c = wn * 32 + ni * 8 + g;
                float y0 = Bs[buf][kb + tg    ][c];
                float y1 = Bs[buf][kb + tg + 4][c];
                f32_split_tf32(y0, bhi[ni][0], blo[ni][0]);
                f32_split_tf32(y1, bhi[ni][1], blo[ni][1]);
            }
#pragma unroll
            for (int mi = 0; mi < 4; mi++)
#pragma unroll
                for (int ni = 0; ni < 4; ni++) {
                    mma_tf32(acc[mi][ni], alo[mi][0], alo[mi][1], alo[mi][2],
                             alo[mi][3], bhi[ni][0], bhi[ni][1]);
                    mma_tf32(acc[mi][ni], ahi[mi][0], ahi[mi][1], ahi[mi][2],
                             ahi[mi][3], blo[ni][0], blo[ni][1]);
                    mma_tf32(acc[mi][ni], ahi[mi][0], ahi[mi][1], ahi[mi][2],
                             ahi[mi][3], bhi[ni][0], bhi[ni][1]);
                }
        }

        if (t + 1 < ntile) {
            buf ^= 1;
            As[buf][ac + 0][ar] = pa0.x; As[buf][ac + 1][ar] = pa0.y;
            As[buf][ac + 2][ar] = pa0.z; As[buf][ac + 3][ar] = pa0.w;
            As[buf][ac + 0][ar + 64] = pa1.x; As[buf][ac + 1][ar + 64] = pa1.y;
            As[buf][ac + 2][ar + 64] = pa1.z; As[buf][ac + 3][ar + 64] = pa1.w;
            *(float4*)&Bs[buf][br][bc]     = pb0;
            *(float4*)&Bs[buf][br + 8][bc] = pb1;
            __syncthreads();
        }
    }

    // ---- epilogue ----
#pragma unroll
    for (int mi = 0; mi < 4; mi++) {
#pragma unroll
        for (int half = 0; half < 2; half++) {
            const int r = row0 + wm * 64 + mi * 16 + g + half * 8;
            if (r >= M) continue;
            size_t obase;
            const float* resrow = nullptr;
            if (EPI == 4) {
                const int bb = r / NPATCH, nn = r - bb * NPATCH;
                obase  = ((size_t)bb * NTOK + nn + 1) * (size_t)N;
                resrow = Res + (size_t)(nn + 1) * N;
            } else {
                obase = (size_t)r * N;
                resrow = Res ? Res + (size_t)r * N : nullptr;
            }
#pragma unroll
            for (int ni = 0; ni < 4; ni++) {
                const int c = col0 + wn * 32 + ni * 8 + tg * 2;
                if (c >= N) continue;
                const float2 bv = *(const float2*)(bias + c);
                float v0 = acc[mi][ni][half * 2 + 0] + bv.x;
                float v1 = acc[mi][ni][half * 2 + 1] + bv.y;
                if (EPI == 1 || EPI == 3) { v0 = gelu_exact(v0); v1 = gelu_exact(v1); }
                if (EPI == 2 || EPI == 3 || EPI == 4) {
                    const float2 rv = *(const float2*)(resrow + c);
                    v0 += rv.x; v1 += rv.y;
                }
                *(float2*)(C + obase + c) = make_float2(v0, v1);
            }
        }
    }
}

// ---------------------------------------------------------------------------
// LayerNorm: warp per row
// ---------------------------------------------------------------------------
__global__ __launch_bounds__(256)
void ln_kernel(const float* __restrict__ X, size_t xstride,
               const float* __restrict__ w, const float* __restrict__ b,
               float* __restrict__ Y, int rows)
{
    const int warp = threadIdx.x >> 5;
    const int lane = threadIdx.x & 31;
    const int row  = blockIdx.x * 8 + warp;
    if (row >= rows) return;
    const float* xr = X + (size_t)row * xstride;
    float v[24];
    float s = 0.f, sq = 0.f;
#pragma unroll
    for (int j = 0; j < 24; j++) {
        v[j] = xr[lane + 32 * j];
        s  += v[j];
        sq += v[j] * v[j];
    }
#pragma unroll
    for (int o = 16; o; o >>= 1) {
        s  += __shfl_xor_sync(0xffffffffu, s,  o);
        sq += __shfl_xor_sync(0xffffffffu, sq, o);
    }
    const float mean = s * (1.0f / DMODEL);
    const float var  = sq * (1.0f / DMODEL) - mean * mean;
    const float rstd = rsqrtf(var + 1e-5f);
#pragma unroll
    for (int j = 0; j < 24; j++) {
        const int d = lane + 32 * j;
        Y[(size_t)row * DMODEL + d] = (v[j] - mean) * rstd * w[d] + b[d];
    }
}

// ---------------------------------------------------------------------------
// Per-token head attention (12x12 softmax over heads)
// ---------------------------------------------------------------------------
__global__ __launch_bounds__(384)
void attn_kernel(const float* __restrict__ QKV, float* __restrict__ O)
{
    const int token = blockIdx.x;
    const int h     = threadIdx.x >> 5;
    const int lane  = threadIdx.x & 31;
    const float* base = QKV + (size_t)token * QKV3;

    const float2 q = *(const float2*)(base + h * DHEAD + 2 * lane);
    float s[NHEADS];
#pragma unroll
    for (int g = 0; g < NHEADS; g++) {
        const float2 kv = *(const float2*)(base + DMODEL + g * DHEAD + 2 * lane);
        float p = q.x * kv.x + q.y * kv.y;
#pragma unroll
        for (int o = 16; o; o >>= 1) p += __shfl_xor_sync(0xffffffffu, p, o);
        s[g] = p * 0.125f;
    }
    float m = s[0];
#pragma unroll
    for (int g = 1; g < NHEADS; g++) m = fmaxf(m, s[g]);
    float sum = 0.f;
#pragma unroll
    for (int g = 0; g < NHEADS; g++) { s[g] = expf(s[g] - m); sum += s[g]; }
    const float inv = 1.0f / sum;
    float o0 = 0.f, o1 = 0.f;
#pragma unroll
    for (int g = 0; g < NHEADS; g++) {
        const float2 vv = *(const float2*)(base + 2 * DMODEL + g * DHEAD + 2 * lane);
        const float a = s[g] * inv;
        o0 += a * vv.x;
        o1 += a * vv.y;
    }
    *(float2*)(O + (size_t)token * DMODEL + h * DHEAD + 2 * lane) = make_float2(o0, o1);
}

// ---------------------------------------------------------------------------
// im2col + cls init
// ---------------------------------------------------------------------------
__global__ __launch_bounds__(256)
void im2col_kernel(const float* __restrict__ X, float* __restrict__ P)
{
    const long long idx = (long long)blockIdx.x * 256 + threadIdx.x;
    if (idx >= (long long)TPAT * DMODEL) return;
    const int k = (int)(idx % DMODEL);
    const int r = (int)(idx / DMODEL);
    const int b = r / NPATCH, n = r - b * NPATCH;
    const int py = n / (IMG / PATCH), px = n - py * (IMG / PATCH);
    const int c = k / (PATCH * PATCH);
    const int rem = k - c * (PATCH * PATCH);
    const int ph = rem / PATCH, pw = rem - ph * PATCH;
    P[idx] = X[(((size_t)b * 3 + c) * IMG + (py * PATCH + ph)) * IMG + (px * PATCH + pw)];
}

__global__ __launch_bounds__(256)
void cls_init_kernel(const float* __restrict__ ce, const float* __restrict__ pe,
                     float* __restrict__ Z)
{
    const int i = blockIdx.x * 256 + threadIdx.x;
    if (i >= BATCH * DMODEL) return;
    const int d = i % DMODEL, b = i / DMODEL;
    Z[(size_t)b * NTOK * DMODEL + d] = ce[d] + pe[d];
}

// ---------------------------------------------------------------------------
// Host launch
// ---------------------------------------------------------------------------
extern "C" void kernel_launch(void* const* d_in, const int* in_sizes, int n_in,
                              void* d_out, int out_size)
{
    (void)in_sizes; (void)n_in; (void)out_size;
    const float* x       = (const float*)d_in[0];
    const float* ce      = (const float*)d_in[1];
    const float* pose    = (const float*)d_in[2];
    const float* proj_w  = (const float*)d_in[3];
    const float* proj_b  = (const float*)d_in[4];
    const float* qkv_w   = (const float*)d_in[5];
    const float* qkv_b   = (const float*)d_in[6];
    const float* top_w   = (const float*)d_in[7];
    const float* top_b   = (const float*)d_in[8];
    const float* ln1_w   = (const float*)d_in[9];
    const float* ln1_b   = (const float*)d_in[10];
    const float* ln2_w   = (const float*)d_in[11];
    const float* ln2_b   = (const float*)d_in[12];
    const float* mlp_w1  = (const float*)d_in[13];
    const float* mlp_b1  = (const float*)d_in[14];
    const float* mlp_w2  = (const float*)d_in[15];
    const float* mlp_b2  = (const float*)d_in[16];
    const float* ln3_w   = (const float*)d_in[17];
    const float* ln3_b   = (const float*)d_in[18];
    const float* head_w1 = (const float*)d_in[19];
    const float* head_b1 = (const float*)d_in[20];
    const float* head_w2 = (const float*)d_in[21];
    const float* head_b2 = (const float*)d_in[22];
    float* out = (float*)d_out;

    float *zp, *hp, *qkvp, *attp, *mlpp, *yp, *t1p;
    cudaGetSymbolAddress((void**)&zp,   g_z);
    cudaGetSymbolAddress((void**)&hp,   g_h);
    cudaGetSymbolAddress((void**)&qkvp, g_qkv);
    cudaGetSymbolAddress((void**)&attp, g_att);
    cudaGetSymbolAddress((void**)&mlpp, g_mlp);
    cudaGetSymbolAddress((void**)&yp,   g_y);
    cudaGetSymbolAddress((void**)&t1p,  g_t1);

    // ---- patch embedding ----
    {
        const long long tot = (long long)TPAT * DMODEL;
        im2col_kernel<<<(unsigned)((tot + 255) / 256), 256>>>(x, qkvp);
        cls_init_kernel<<<(BATCH * DMODEL + 255) / 256, 256>>>(ce, pose, zp);
        dim3 grid(DMODEL / BN, (TPAT + BM - 1) / BM);
        gemm_tc<4><<<grid, 256>>>(qkvp, proj_w, proj_b, pose, zp,
                                  TPAT, DMODEL, DMODEL);
    }

    const int lnGrid = (TTOK + 7) / 8;

    for (int i = 0; i < NLAYERS; i++) {
        ln_kernel<<<lnGrid, 256>>>(zp, DMODEL, ln1_w + (size_t)i * DMODEL,
                                   ln1_b + (size_t)i * DMODEL, hp, TTOK);
        {
            dim3 grid(QKV3 / BN, (TTOK + BM - 1) / BM);
            gemm_tc<0><<<grid, 256>>>(hp, qkv_w + (size_t)i * DMODEL * QKV3,
                                      qkv_b + (size_t)i * QKV3, nullptr, qkvp,
                                      TTOK, QKV3, DMODEL);
        }
        attn_kernel<<<TTOK, 384>>>(qkvp, attp);
        {
            dim3 grid(DMODEL / BN, (TTOK + BM - 1) / BM);
            gemm_tc<2><<<grid, 256>>>(attp, top_w + (size_t)i * DMODEL * DMODEL,
                                      top_b + (size_t)i * DMODEL, zp, zp,
                                      TTOK, DMODEL, DMODEL);
        }
        ln_kernel<<<lnGrid, 256>>>(zp, DMODEL, ln2_w + (size_t)i * DMODEL,
                                   ln2_b + (size_t)i * DMODEL, hp, TTOK);
        {
            dim3 grid(DMLP / BN, (TTOK + BM - 1) / BM);
            gemm_tc<1><<<grid, 256>>>(hp, mlp_w1 + (size_t)i * DMODEL * DMLP,
                                      mlp_b1 + (size_t)i * DMLP, nullptr, mlpp,
                                      TTOK, DMLP, DMODEL);
        }
        {
            dim3 grid(DMODEL / BN, (TTOK + BM - 1) / BM);
            gemm_tc<3><<<grid, 256>>>(mlpp, mlp_w2 + (size_t)i * DMLP * DMODEL,
                                      mlp_b2 + (size_t)i * DMODEL, zp, zp,
                                      TTOK, DMODEL, DMLP);
        }
    }

    // ---- classification head ----
    ln_kernel<<<(BATCH + 7) / 8, 256>>>(zp, (size_t)NTOK * DMODEL, ln3_w, ln3_b,
                                        yp, BATCH);
    {
        dim3 grid(DMLP / BN, (BATCH + BM - 1) / BM);
        gemm_tc<1><<<grid, 256>>>(yp, head_w1, head_b1, nullptr, t1p,
                                  BATCH, DMLP, DMODEL);
    }
    {
        dim3 grid((NCLASSES + BN - 1) / BN, (BATCH + BM - 1) / BM);
        gemm_tc<1><<<grid, 256>>>(t1p, head_w2, head_b2, nullptr, out,
                                  BATCH, NCLASSES, DMLP);
    }
}

// round 3
// speedup vs baseline: 2.2750x; 2.1287x over previous
#include <cuda_runtime.h>
#include <cuda_bf16.h>
#include <math.h>
#include <stdint.h>

// ---------------------------------------------------------------------------
// Problem constants
// ---------------------------------------------------------------------------
#define PATCH     16
#define IMG       384
#define DMODEL    768
#define DMLP      3072
#define NLAYERS   12
#define NHEADS    12
#define DHEAD     64
#define NCLASSES  1000
#define BATCH     64
#define NPATCH    576
#define NTOK      577
#define TTOK      (BATCH * NTOK)   // 36928
#define TPAT      (BATCH * NPATCH) // 36864
#define QKV3      (3 * DMODEL)     // 2304

// ---------------------------------------------------------------------------
// Scratch
// ---------------------------------------------------------------------------
__device__ float g_z  [(size_t)TTOK * DMODEL];
__device__ float g_h  [(size_t)TTOK * DMODEL];
__device__ float g_qkv[(size_t)TTOK * QKV3];
__device__ float g_att[(size_t)TTOK * DMODEL];
__device__ float g_mlp[(size_t)TTOK * DMLP];
__device__ float g_y  [(size_t)BATCH * DMODEL];
__device__ float g_t1 [(size_t)BATCH * DMLP];

// ---------------------------------------------------------------------------
// Helpers
// ---------------------------------------------------------------------------
__device__ __forceinline__ float gelu_exact(float x) {
    return 0.5f * x * (1.0f + erff(x * 0.70710678118654752f));
}

__device__ __forceinline__ uint32_t packbf(__nv_bfloat16 a, __nv_bfloat16 b) {
    __nv_bfloat162 t = __halves2bfloat162(a, b);
    return *reinterpret_cast<uint32_t*>(&t);
}

// split (x0,x1) into hi (bf16 pair) and lo (bf16 residual pair)
__device__ __forceinline__ void split2(float x0, float x1,
                                       uint32_t& hi, uint32_t& lo) {
    __nv_bfloat16 h0 = __float2bfloat16_rn(x0);
    __nv_bfloat16 h1 = __float2bfloat16_rn(x1);
    __nv_bfloat16 l0 = __float2bfloat16_rn(x0 - __bfloat162float(h0));
    __nv_bfloat16 l1 = __float2bfloat16_rn(x1 - __bfloat162float(h1));
    hi = packbf(h0, h1);
    lo = packbf(l0, l1);
}

__device__ __forceinline__ void mma_bf16(float c[4], const uint32_t a[4],
                                         const uint32_t b[2]) {
    asm volatile(
        "mma.sync.aligned.m16n8k16.row.col.f32.bf16.bf16.f32 "
        "{%0,%1,%2,%3}, {%4,%5,%6,%7}, {%8,%9}, {%0,%1,%2,%3};\n"
        : "+f"(c[0]), "+f"(c[1]), "+f"(c[2]), "+f"(c[3])
        : "r"(a[0]), "r"(a[1]), "r"(a[2]), "r"(a[3]), "r"(b[0]), "r"(b[1]));
}

// ---------------------------------------------------------------------------
// Tensor-core GEMM (bf16 hi/lo split, 3 MMAs): C = epi(A@B + bias)(+res)
// EPI: 0 bias | 1 gelu | 2 bias+res | 3 gelu+res | 4 bias+pose(remap rows)
// Block 128x128 x k16, 256 threads, 8 warps of 64x32 (m16n8k16).
// Smem holds k-pair-packed bf16 hi/lo tiles; fragment loads are single LDS32.
// ---------------------------------------------------------------------------
#define BM 128
#define BN 128
#define BKT 16
#define KP  8                 // k-pairs per tile
#define ASTR (BM + 8)
#define BSTR (BN + 8)
#define A_WORDS (2 * 2 * KP * ASTR)             // [buf][split][kp][row]
#define B_WORDS (2 * 2 * KP * BSTR)
#define SMEM_BYTES ((A_WORDS + B_WORDS) * 4)

template<int EPI>
__global__ __launch_bounds__(256)
void gemm_tc(const float* __restrict__ A, const float* __restrict__ B,
             const float* __restrict__ bias, const float* Res,
             float* C, int M, int N, int K)
{
    extern __shared__ uint32_t smem[];
    uint32_t* const Asm = smem;                 // A: [buf][s][kp][ASTR]
    uint32_t* const Bsm = smem + A_WORDS;       // B: [buf][s][kp][BSTR]

    const int tid  = threadIdx.x;
    const int lane = tid & 31;
    const int warp = tid >> 5;
    const int wm   = warp >> 2;   // 0..1
    const int wn   = warp & 3;    // 0..3
    const int g    = lane >> 2;   // 0..7
    const int tg   = lane & 3;    // 0..3

    const int row0 = blockIdx.y * BM;
    const int col0 = blockIdx.x * BN;

    // loader mapping
    const int ar = tid >> 2;          // A row 0..63 (+64)
    const int ac = (tid & 3) * 4;     // A k offset {0,4,8,12}
    const int akp = ac >> 1;          // k-pair {0,2,4,6}
    const int brp = tid >> 5;         // B k-pair 0..7
    const int bc  = (tid & 31) * 4;   // B col offset

    const float4 z4 = make_float4(0.f, 0.f, 0.f, 0.f);

    float acc[4][4][4];
#pragma unroll
    for (int i = 0; i < 4; i++)
#pragma unroll
        for (int j = 0; j < 4; j++)
#pragma unroll
            for (int q = 0; q < 4; q++) acc[i][j][q] = 0.f;

    // store one A float4 (row r, kpairs akp, akp+1) into buf
    auto storeA = [&](int buf, float4 v, int r) {
        uint32_t h0, l0, h1, l1;
        split2(v.x, v.y, h0, l0);
        split2(v.z, v.w, h1, l1);
        uint32_t* hi = Asm + ((buf * 2 + 0) * KP) * ASTR;
        uint32_t* lo = Asm + ((buf * 2 + 1) * KP) * ASTR;
        hi[(akp    ) * ASTR + r] = h0;
        hi[(akp + 1) * ASTR + r] = h1;
        lo[(akp    ) * ASTR + r] = l0;
        lo[(akp + 1) * ASTR + r] = l1;
    };
    // store B kpair (rows k,k+1 float4 along n) into buf
    auto storeB = [&](int buf, float4 r0, float4 r1) {
        uint4 hi4, lo4;
        split2(r0.x, r1.x, hi4.x, lo4.x);
        split2(r0.y, r1.y, hi4.y, lo4.y);
        split2(r0.z, r1.z, hi4.z, lo4.z);
        split2(r0.w, r1.w, hi4.w, lo4.w);
        *(uint4*)(Bsm + ((buf * 2 + 0) * KP + brp) * BSTR + bc) = hi4;
        *(uint4*)(Bsm + ((buf * 2 + 1) * KP + brp) * BSTR + bc) = lo4;
    };

    // ---- load tile 0 ----
    {
        const int r1 = row0 + ar, r2 = row0 + ar + 64;
        float4 a0 = (r1 < M) ? *(const float4*)(A + (size_t)r1 * K + ac) : z4;
        float4 a1 = (r2 < M) ? *(const float4*)(A + (size_t)r2 * K + ac) : z4;
        storeA(0, a0, ar);
        storeA(0, a1, ar + 64);
        const int c = col0 + bc;
        float4 b0 = z4, b1 = z4;
        if (c < N) {
            b0 = *(const float4*)(B + (size_t)(2 * brp) * N + c);
            b1 = *(const float4*)(B + (size_t)(2 * brp + 1) * N + c);
        }
        storeB(0, b0, b1);
    }
    __syncthreads();

    const int ntile = K / BKT;
    int buf = 0;
    float4 pa0, pa1, pb0, pb1;

    for (int t = 0; t < ntile; ++t) {
        if (t + 1 < ntile) {
            const int kt = (t + 1) * BKT;
            const int r1 = row0 + ar, r2 = row0 + ar + 64;
            pa0 = (r1 < M) ? *(const float4*)(A + (size_t)r1 * K + kt + ac) : z4;
            pa1 = (r2 < M) ? *(const float4*)(A + (size_t)r2 * K + kt + ac) : z4;
            const int c = col0 + bc;
            if (c < N) {
                pb0 = *(const float4*)(B + (size_t)(kt + 2 * brp) * N + c);
                pb1 = *(const float4*)(B + (size_t)(kt + 2 * brp + 1) * N + c);
            } else { pb0 = z4; pb1 = z4; }
        }

        // ---- fragment loads (single LDS32 each, conflict-free) ----
        uint32_t afr[2][4][4];   // [split][mi][reg]
        uint32_t bfr[2][4][2];   // [split][ni][reg]
#pragma unroll
        for (int s = 0; s < 2; s++) {
            const uint32_t* ab = Asm + ((buf * 2 + s) * KP) * ASTR;
#pragma unroll
            for (int mi = 0; mi < 4; mi++) {
                const int r = wm * 64 + mi * 16 + g;
                afr[s][mi][0] = ab[(tg    ) * ASTR + r];
                afr[s][mi][1] = ab[(tg    ) * ASTR + r + 8];
                afr[s][mi][2] = ab[(tg + 4) * ASTR + r];
                afr[s][mi][3] = ab[(tg + 4) * ASTR + r + 8];
            }
            const uint32_t* bb = Bsm + ((buf * 2 + s) * KP) * BSTR;
#pragma unroll
            for (int ni = 0; ni < 4; ni++) {
                const int c = wn * 32 + ni * 8 + g;
                bfr[s][ni][0] = bb[(tg    ) * BSTR + c];
                bfr[s][ni][1] = bb[(tg + 4) * BSTR + c];
            }
        }
#pragma unroll
        for (int mi = 0; mi < 4; mi++)
#pragma unroll
            for (int ni = 0; ni < 4; ni++) {
                mma_bf16(acc[mi][ni], afr[0][mi], bfr[0][ni]);   // hi*hi
                mma_bf16(acc[mi][ni], afr[0][mi], bfr[1][ni]);   // hi*lo
                mma_bf16(acc[mi][ni], afr[1][mi], bfr[0][ni]);   // lo*hi
            }

        if (t + 1 < ntile) {
            const int nb = buf ^ 1;
            storeA(nb, pa0, ar);
            storeA(nb, pa1, ar + 64);
            storeB(nb, pb0, pb1);
            __syncthreads();
            buf = nb;
        }
    }

    // ---- epilogue ----
#pragma unroll
    for (int mi = 0; mi < 4; mi++) {
#pragma unroll
        for (int half = 0; half < 2; half++) {
            const int r = row0 + wm * 64 + mi * 16 + g + half * 8;
            if (r >= M) continue;
            size_t obase;
            const float* resrow = nullptr;
            if (EPI == 4) {
                const int bb = r / NPATCH, nn = r - bb * NPATCH;
                obase  = ((size_t)bb * NTOK + nn + 1) * (size_t)N;
                resrow = Res + (size_t)(nn + 1) * N;
            } else {
                obase = (size_t)r * N;
                if (EPI == 2 || EPI == 3) resrow = Res + (size_t)r * N;
            }
#pragma unroll
            for (int ni = 0; ni < 4; ni++) {
                const int c = col0 + wn * 32 + ni * 8 + tg * 2;
                if (c >= N) continue;
                const float2 bv = *(const float2*)(bias + c);
                float v0 = acc[mi][ni][half * 2 + 0] + bv.x;
                float v1 = acc[mi][ni][half * 2 + 1] + bv.y;
                if (EPI == 1 || EPI == 3) { v0 = gelu_exact(v0); v1 = gelu_exact(v1); }
                if (EPI == 2 || EPI == 3 || EPI == 4) {
                    const float2 rv = *(const float2*)(resrow + c);
                    v0 += rv.x; v1 += rv.y;
                }
                *(float2*)(C + obase + c) = make_float2(v0, v1);
            }
        }
    }
}

// ---------------------------------------------------------------------------
// LayerNorm: warp per row
// ---------------------------------------------------------------------------
__global__ __launch_bounds__(256)
void ln_kernel(const float* __restrict__ X, size_t xstride,
               const float* __restrict__ w, const float* __restrict__ b,
               float* __restrict__ Y, int rows)
{
    const int warp = threadIdx.x >> 5;
    const int lane = threadIdx.x & 31;
    const int row  = blockIdx.x * 8 + warp;
    if (row >= rows) return;
    const float* xr = X + (size_t)row * xstride;
    float v[24];
    float s = 0.f, sq = 0.f;
#pragma unroll
    for (int j = 0; j < 24; j++) {
        v[j] = xr[lane + 32 * j];
        s  += v[j];
        sq += v[j] * v[j];
    }
#pragma unroll
    for (int o = 16; o; o >>= 1) {
        s  += __shfl_xor_sync(0xffffffffu, s,  o);
        sq += __shfl_xor_sync(0xffffffffu, sq, o);
    }
    const float mean = s * (1.0f / DMODEL);
    const float var  = sq * (1.0f / DMODEL) - mean * mean;
    const float rstd = rsqrtf(var + 1e-5f);
#pragma unroll
    for (int j = 0; j < 24; j++) {
        const int d = lane + 32 * j;
        Y[(size_t)row * DMODEL + d] = (v[j] - mean) * rstd * w[d] + b[d];
    }
}

// ---------------------------------------------------------------------------
// Per-token head attention (12x12 softmax over heads)
// ---------------------------------------------------------------------------
__global__ __launch_bounds__(384)
void attn_kernel(const float* __restrict__ QKV, float* __restrict__ O)
{
    const int token = blockIdx.x;
    const int h     = threadIdx.x >> 5;
    const int lane  = threadIdx.x & 31;
    const float* base = QKV + (size_t)token * QKV3;

    const float2 q = *(const float2*)(base + h * DHEAD + 2 * lane);
    float s[NHEADS];
#pragma unroll
    for (int g = 0; g < NHEADS; g++) {
        const float2 kv = *(const float2*)(base + DMODEL + g * DHEAD + 2 * lane);
        float p = q.x * kv.x + q.y * kv.y;
#pragma unroll
        for (int o = 16; o; o >>= 1) p += __shfl_xor_sync(0xffffffffu, p, o);
        s[g] = p * 0.125f;
    }
    float m = s[0];
#pragma unroll
    for (int g = 1; g < NHEADS; g++) m = fmaxf(m, s[g]);
    float sum = 0.f;
#pragma unroll
    for (int g = 0; g < NHEADS; g++) { s[g] = expf(s[g] - m); sum += s[g]; }
    const float inv = 1.0f / sum;
    float o0 = 0.f, o1 = 0.f;
#pragma unroll
    for (int g = 0; g < NHEADS; g++) {
        const float2 vv = *(const float2*)(base + 2 * DMODEL + g * DHEAD + 2 * lane);
        const float a = s[g] * inv;
        o0 += a * vv.x;
        o1 += a * vv.y;
    }
    *(float2*)(O + (size_t)token * DMODEL + h * DHEAD + 2 * lane) = make_float2(o0, o1);
}

// ---------------------------------------------------------------------------
// im2col + cls init
// ---------------------------------------------------------------------------
__global__ __launch_bounds__(256)
void im2col_kernel(const float* __restrict__ X, float* __restrict__ P)
{
    const long long idx = (long long)blockIdx.x * 256 + threadIdx.x;
    if (idx >= (long long)TPAT * DMODEL) return;
    const int k = (int)(idx % DMODEL);
    const int r = (int)(idx / DMODEL);
    const int b = r / NPATCH, n = r - b * NPATCH;
    const int py = n / (IMG / PATCH), px = n - py * (IMG / PATCH);
    const int c = k / (PATCH * PATCH);
    const int rem = k - c * (PATCH * PATCH);
    const int ph = rem / PATCH, pw = rem - ph * PATCH;
    P[idx] = X[(((size_t)b * 3 + c) * IMG + (py * PATCH + ph)) * IMG + (px * PATCH + pw)];
}

__global__ __launch_bounds__(256)
void cls_init_kernel(const float* __restrict__ ce, const float* __restrict__ pe,
                     float* __restrict__ Z)
{
    const int i = blockIdx.x * 256 + threadIdx.x;
    if (i >= BATCH * DMODEL) return;
    const int d = i % DMODEL, b = i / DMODEL;
    Z[(size_t)b * NTOK * DMODEL + d] = ce[d] + pe[d];
}

// ---------------------------------------------------------------------------
// Host launch
// ---------------------------------------------------------------------------
extern "C" void kernel_launch(void* const* d_in, const int* in_sizes, int n_in,
                              void* d_out, int out_size)
{
    (void)in_sizes; (void)n_in; (void)out_size;
    const float* x       = (const float*)d_in[0];
    const float* ce      = (const float*)d_in[1];
    const float* pose    = (const float*)d_in[2];
    const float* proj_w  = (const float*)d_in[3];
    const float* proj_b  = (const float*)d_in[4];
    const float* qkv_w   = (const float*)d_in[5];
    const float* qkv_b   = (const float*)d_in[6];
    const float* top_w   = (const float*)d_in[7];
    const float* top_b   = (const float*)d_in[8];
    const float* ln1_w   = (const float*)d_in[9];
    const float* ln1_b   = (const float*)d_in[10];
    const float* ln2_w   = (const float*)d_in[11];
    const float* ln2_b   = (const float*)d_in[12];
    const float* mlp_w1  = (const float*)d_in[13];
    const float* mlp_b1  = (const float*)d_in[14];
    const float* mlp_w2  = (const float*)d_in[15];
    const float* mlp_b2  = (const float*)d_in[16];
    const float* ln3_w   = (const float*)d_in[17];
    const float* ln3_b   = (const float*)d_in[18];
    const float* head_w1 = (const float*)d_in[19];
    const float* head_b1 = (const float*)d_in[20];
    const float* head_w2 = (const float*)d_in[21];
    const float* head_b2 = (const float*)d_in[22];
    float* out = (float*)d_out;

    float *zp, *hp, *qkvp, *attp, *mlpp, *yp, *t1p;
    cudaGetSymbolAddress((void**)&zp,   g_z);
    cudaGetSymbolAddress((void**)&hp,   g_h);
    cudaGetSymbolAddress((void**)&qkvp, g_qkv);
    cudaGetSymbolAddress((void**)&attp, g_att);
    cudaGetSymbolAddress((void**)&mlpp, g_mlp);
    cudaGetSymbolAddress((void**)&yp,   g_y);
    cudaGetSymbolAddress((void**)&t1p,  g_t1);

    cudaFuncSetAttribute(gemm_tc<0>, cudaFuncAttributeMaxDynamicSharedMemorySize, SMEM_BYTES);
    cudaFuncSetAttribute(gemm_tc<1>, cudaFuncAttributeMaxDynamicSharedMemorySize, SMEM_BYTES);
    cudaFuncSetAttribute(gemm_tc<2>, cudaFuncAttributeMaxDynamicSharedMemorySize, SMEM_BYTES);
    cudaFuncSetAttribute(gemm_tc<3>, cudaFuncAttributeMaxDynamicSharedMemorySize, SMEM_BYTES);
    cudaFuncSetAttribute(gemm_tc<4>, cudaFuncAttributeMaxDynamicSharedMemorySize, SMEM_BYTES);

    // ---- patch embedding ----
    {
        const long long tot = (long long)TPAT * DMODEL;
        im2col_kernel<<<(unsigned)((tot + 255) / 256), 256>>>(x, qkvp);
        cls_init_kernel<<<(BATCH * DMODEL + 255) / 256, 256>>>(ce, pose, zp);
        dim3 grid(DMODEL / BN, (TPAT + BM - 1) / BM);
        gemm_tc<4><<<grid, 256, SMEM_BYTES>>>(qkvp, proj_w, proj_b, pose, zp,
                                              TPAT, DMODEL, DMODEL);
    }

    const int lnGrid = (TTOK + 7) / 8;

    for (int i = 0; i < NLAYERS; i++) {
        ln_kernel<<<lnGrid, 256>>>(zp, DMODEL, ln1_w + (size_t)i * DMODEL,
                                   ln1_b + (size_t)i * DMODEL, hp, TTOK);
        {
            dim3 grid(QKV3 / BN, (TTOK + BM - 1) / BM);
            gemm_tc<0><<<grid, 256, SMEM_BYTES>>>(hp, qkv_w + (size_t)i * DMODEL * QKV3,
                                                  qkv_b + (size_t)i * QKV3, nullptr, qkvp,
                                                  TTOK, QKV3, DMODEL);
        }
        attn_kernel<<<TTOK, 384>>>(qkvp, attp);
        {
            dim3 grid(DMODEL / BN, (TTOK + BM - 1) / BM);
            gemm_tc<2><<<grid, 256, SMEM_BYTES>>>(attp, top_w + (size_t)i * DMODEL * DMODEL,
                                                  top_b + (size_t)i * DMODEL, zp, zp,
                                                  TTOK, DMODEL, DMODEL);
        }
        ln_kernel<<<lnGrid, 256>>>(zp, DMODEL, ln2_w + (size_t)i * DMODEL,
                                   ln2_b + (size_t)i * DMODEL, hp, TTOK);
        {
            dim3 grid(DMLP / BN, (TTOK + BM - 1) / BM);
            gemm_tc<1><<<grid, 256, SMEM_BYTES>>>(hp, mlp_w1 + (size_t)i * DMODEL * DMLP,
                                                  mlp_b1 + (size_t)i * DMLP, nullptr, mlpp,
                                                  TTOK, DMLP, DMODEL);
        }
        {
            dim3 grid(DMODEL / BN, (TTOK + BM - 1) / BM);
            gemm_tc<3><<<grid, 256, SMEM_BYTES>>>(mlpp, mlp_w2 + (size_t)i * DMLP * DMODEL,
                                                  mlp_b2 + (size_t)i * DMODEL, zp, zp,
                                                  TTOK, DMODEL, DMLP);
        }
    }

    // ---- classification head ----
    ln_kernel<<<(BATCH + 7) / 8, 256>>>(zp, (size_t)NTOK * DMODEL, ln3_w, ln3_b,
                                        yp, BATCH);
    {
        dim3 grid(DMLP / BN, (BATCH + BM - 1) / BM);
        gemm_tc<1><<<grid, 256, SMEM_BYTES>>>(yp, head_w1, head_b1, nullptr, t1p,
                                              BATCH, DMLP, DMODEL);
    }
    {
        dim3 grid((NCLASSES + BN - 1) / BN, (BATCH + BM - 1) / BM);
        gemm_tc<1><<<grid, 256, SMEM_BYTES>>>(t1p, head_w2, head_b2, nullptr, out,
                                              BATCH, NCLASSES, DMLP);
    }
}